// round 9
// baseline (speedup 1.0000x reference)
#include <cuda_runtime.h>
#include <cuda_bf16.h>
#include <math.h>
#include <stdint.h>

// ContrastiveLoss via warp-level bf16 mma.sync (HMMA), persistent tile kernel.
// loss = log(S_A_up + S_C_up + S_B_full + sim_s) - log(sim_s)
//   A=UU^T, C=VV^T, B=UV^T on L2-normalized halves.
//   sim_s = sum exp(diag(B)/2), harvested from the 32 diagonal B tiles.
//
// g_xb: 64 bands of 128 rows; band = 4 K-blocks of 64 bf16 = 128 rows x 128B,
// SW128-swizzled, 16KB contiguous -> cp.async.bulk feeds MMA smem directly.
//
// tile_k: 296 persistent CTAs (2/SM), each strides tiles t = bid + 296*i.
// Continuous double-buffered chunk stream across tiles: next tile's loads
// overlap current tile's epilogue. Mainloop/epilogue identical to the
// verified 53.6us R5 kernel.

#define D      256
#define NROWS  8192
#define NT     32
#define NTILES 2080
#define GRID   296
#define BAND_BYTES 65536
#define KBLK_BYTES 16384
#define STAGE_BYTES 32768              // A 16KB + B 16KB
#define SMEM_DATA   1024
#define SMEM_TOTAL  (SMEM_DATA + 2 * STAGE_BYTES)   // 66560

#define MB_FULL0  16
#define MB_FULL1  24
#define MB_EMPTY0 32
#define MB_EMPTY1 40

__device__ __align__(128) uint8_t g_xb[NROWS * D * 2];   // 4 MB bf16 swizzled
__device__ double g_main;
__device__ double g_sims;

// ---------------------------------------------------------------------------
static __device__ __forceinline__ uint32_t smem_u32(const void* p) {
    uint32_t a;
    asm("{ .reg .u64 t; cvta.to.shared.u64 t, %1; cvt.u32.u64 %0, t; }"
        : "=r"(a) : "l"(p));
    return a;
}

static __device__ __forceinline__ float ex2f(float x) {
    float y;
    asm("ex2.approx.f32 %0, %1;" : "=f"(y) : "f"(x));
    return y;
}
#define EXP_HALF_LOG2E 0.7213475204444817f   // 0.5 * log2(e)

#define MBAR_INIT(addr, cnt) \
    asm volatile("mbarrier.init.shared.b64 [%0], %1;" :: "r"(addr), "r"(cnt) : "memory")

#define MBAR_ARRIVE(addr) \
    asm volatile("mbarrier.arrive.shared.b64 _, [%0];" :: "r"(addr) : "memory")

#define MBAR_EXPECT_TX(addr, bytes) \
    asm volatile("mbarrier.arrive.expect_tx.shared.b64 _, [%0], %1;" \
                 :: "r"(addr), "r"(bytes) : "memory")

#define MBAR_WAIT(addr, parity) do {                                          \
    uint32_t _m = (addr); uint32_t _p = (parity); uint32_t _done;             \
    asm volatile("{\n\t.reg .pred p;\n\t"                                     \
        "mbarrier.try_wait.parity.acquire.cta.shared::cta.b64 p, [%1], %2;\n\t"\
        "selp.b32 %0, 1, 0, p;\n\t}"                                          \
        : "=r"(_done) : "r"(_m), "r"(_p) : "memory");                         \
    if (!_done) {                                                             \
        asm volatile("{\n\t.reg .pred P1;\n\t"                                \
            "W_%=:\n\t"                                                       \
            "mbarrier.try_wait.parity.acquire.cta.shared::cta.b64 P1, [%0], %1, 0x989680;\n\t" \
            "@P1 bra.uni WD_%=;\n\t"                                          \
            "bra.uni W_%=;\n\t"                                               \
            "WD_%=:\n\t}" :: "r"(_m), "r"(_p) : "memory");                    \
    }                                                                         \
} while (0)

#define BULK_G2S(dst, src, bytes, mbar) \
    asm volatile("cp.async.bulk.shared::cta.global.mbarrier::complete_tx::bytes [%0], [%1], %2, [%3];" \
                 :: "r"(dst), "l"(src), "r"(bytes), "r"(mbar) : "memory")

static __device__ __forceinline__ void ldsm_x4(uint32_t* r, uint32_t addr) {
    asm volatile("ldmatrix.sync.aligned.m8n8.x4.shared.b16 {%0,%1,%2,%3}, [%4];"
                 : "=r"(r[0]), "=r"(r[1]), "=r"(r[2]), "=r"(r[3]) : "r"(addr));
}

static __device__ __forceinline__ void mma16816(float* d, const uint32_t* a,
                                                uint32_t b0, uint32_t b1) {
    asm volatile("mma.sync.aligned.m16n8k16.row.col.f32.bf16.bf16.f32 "
                 "{%0,%1,%2,%3}, {%4,%5,%6,%7}, {%8,%9}, {%0,%1,%2,%3};"
                 : "+f"(d[0]), "+f"(d[1]), "+f"(d[2]), "+f"(d[3])
                 : "r"(a[0]), "r"(a[1]), "r"(a[2]), "r"(a[3]), "r"(b0), "r"(b1));
}

// Tile decode: t in [0, NTILES) -> flags + band pointers.
static __device__ __forceinline__ void tdecode(int t, bool& maskt, bool& bdiag,
                                               const uint8_t*& gA, const uint8_t*& gB) {
    maskt = false; bdiag = false;
    if (t < 1024) {                       // B = U V^T, full
        int bi = t >> 5, bj = t & 31;
        bdiag = (bi == bj);
        gA = g_xb + (size_t)bi * BAND_BYTES;
        gB = g_xb + (size_t)(32 + bj) * BAND_BYTES;
    } else {                              // A (m=0) / C (m=1), upper
        t -= 1024;
        int m = (t >= 528) ? 1 : 0;
        int u = t - m * 528;
        int b_ = 0;
        while (u >= NT - b_) { u -= NT - b_; b_++; }
        int bi = b_, bj = b_ + u;
        maskt = (bi == bj);
        gA = g_xb + (size_t)(m * 32 + bi) * BAND_BYTES;
        gB = g_xb + (size_t)(m * 32 + bj) * BAND_BYTES;
    }
}

// ---------------------------------------------------------------------------
// Warp per row: L2 norm -> bf16 normalized row into swizzled band layout.
// Block 0 also zeroes global accumulators (stream-ordered before tile_k).
__global__ __launch_bounds__(256) void normalize_k(const float* __restrict__ x) {
    const int tid  = threadIdx.x;
    const int wid  = tid >> 5;
    const int lane = tid & 31;
    const int row  = blockIdx.x * 8 + wid;
    if (blockIdx.x == 0 && tid == 0) { g_main = 0.0; g_sims = 0.0; }

    const float4* xr = (const float4*)(x + row * D);
    float4 v0 = xr[lane * 2 + 0];
    float4 v1 = xr[lane * 2 + 1];

    float ss = v0.x * v0.x + v0.y * v0.y + v0.z * v0.z + v0.w * v0.w
             + v1.x * v1.x + v1.y * v1.y + v1.z * v1.z + v1.w * v1.w;
    #pragma unroll
    for (int o = 16; o > 0; o >>= 1) ss += __shfl_xor_sync(0xFFFFFFFFu, ss, o);
    float inv = 1.0f / fmaxf(sqrtf(ss), 1e-8f);

    uint32_t p[4];
    p[0] = (uint32_t)__bfloat16_as_ushort(__float2bfloat16(v0.x * inv))
         | ((uint32_t)__bfloat16_as_ushort(__float2bfloat16(v0.y * inv)) << 16);
    p[1] = (uint32_t)__bfloat16_as_ushort(__float2bfloat16(v0.z * inv))
         | ((uint32_t)__bfloat16_as_ushort(__float2bfloat16(v0.w * inv)) << 16);
    p[2] = (uint32_t)__bfloat16_as_ushort(__float2bfloat16(v1.x * inv))
         | ((uint32_t)__bfloat16_as_ushort(__float2bfloat16(v1.y * inv)) << 16);
    p[3] = (uint32_t)__bfloat16_as_ushort(__float2bfloat16(v1.z * inv))
         | ((uint32_t)__bfloat16_as_ushort(__float2bfloat16(v1.w * inv)) << 16);

    int band = row >> 7, rib = row & 127;
    int kb = lane >> 3;
    uint32_t off = (uint32_t)(rib * 128 + (lane & 7) * 16);
    off ^= (off >> 3) & 0x70;                             // SW128
    *(uint4*)(g_xb + (size_t)band * BAND_BYTES + (size_t)kb * KBLK_BYTES + off)
        = *(uint4*)p;
}

// ---------------------------------------------------------------------------
// Persistent: each CTA processes tiles t = blockIdx.x + GRID*i.
__global__ __launch_bounds__(256, 2) void tile_k() {
    extern __shared__ __align__(1024) uint8_t smem[];
    uint32_t sb = smem_u32(smem);
    const int tid  = threadIdx.x;
    const int wid  = tid >> 5;
    const int lane = tid & 31;

    const int ntm = (NTILES - (int)blockIdx.x + GRID - 1) / GRID;   // 7 or 8
    const int nq  = ntm * 4;

    if (tid == 0) {
        MBAR_INIT(sb + MB_FULL0, 1);  MBAR_INIT(sb + MB_FULL1, 1);
        MBAR_INIT(sb + MB_EMPTY0, 8); MBAR_INIT(sb + MB_EMPTY1, 8);
    }
    __syncthreads();

    // Producer prologue: chunks 0,1 of first tile.
    if (tid == 0) {
        bool mt, bd; const uint8_t *pA, *pB;
        tdecode((int)blockIdx.x, mt, bd, pA, pB);
        MBAR_EXPECT_TX(sb + MB_FULL0, (uint32_t)STAGE_BYTES);
        BULK_G2S(sb + SMEM_DATA,          pA, KBLK_BYTES, sb + MB_FULL0);
        BULK_G2S(sb + SMEM_DATA + 16384,  pB, KBLK_BYTES, sb + MB_FULL0);
        MBAR_EXPECT_TX(sb + MB_FULL1, (uint32_t)STAGE_BYTES);
        BULK_G2S(sb + SMEM_DATA + STAGE_BYTES,         pA + KBLK_BYTES, KBLK_BYTES, sb + MB_FULL1);
        BULK_G2S(sb + SMEM_DATA + STAGE_BYTES + 16384, pB + KBLK_BYTES, KBLK_BYTES, sb + MB_FULL1);
    }

    // ---- per-warp / per-lane ldmatrix geometry (verified R3/R5) ----
    const int warp_m = wid & 3;          // 32-row strip
    const int warp_n = wid >> 2;         // 64-col strip
    const int lrow = lane & 15;
    const uint32_t xoff = ((lane >> 4) & 1) * 16;

    uint32_t aRow[2], aSw[2], bRow[4], bSw[4];
    #pragma unroll
    for (int am = 0; am < 2; am++) {
        int r = warp_m * 32 + am * 16 + lrow;
        aRow[am] = (uint32_t)(r * 128);
        aSw[am]  = (uint32_t)((r & 7) << 4);
    }
    #pragma unroll
    for (int bg = 0; bg < 4; bg++) {
        int r = warp_n * 64 + bg * 16 + lrow;
        bRow[bg] = (uint32_t)(r * 128);
        bSw[bg]  = (uint32_t)((r & 7) << 4);
    }

    const int rbase = warp_m * 32 + (lane >> 2);
    const int cbase = warp_n * 64 + 2 * (lane & 3);

    float d[2][8][4];
    #pragma unroll
    for (int i = 0; i < 2; i++)
        #pragma unroll
        for (int j = 0; j < 8; j++)
            #pragma unroll
            for (int k = 0; k < 4; k++) d[i][j][k] = 0.0f;

    float lsum = 0.0f, lsumd = 0.0f;
    int fp0 = 0, fp1 = 0, ep0 = 0, ep1 = 0;

    for (int q = 0; q < nq; q++) {
        const int st = q & 1;
        const uint32_t stA = sb + SMEM_DATA + st * STAGE_BYTES;
        const uint32_t stB = stA + 16384;

        if (st == 0) { MBAR_WAIT(sb + MB_FULL0, (uint32_t)fp0); fp0 ^= 1; }
        else         { MBAR_WAIT(sb + MB_FULL1, (uint32_t)fp1); fp1 ^= 1; }

        #pragma unroll
        for (int ks = 0; ks < 4; ks++) {
            const uint32_t kc = (uint32_t)(ks * 32);
            uint32_t a[2][4], b[4][4];
            #pragma unroll
            for (int am = 0; am < 2; am++)
                ldsm_x4(a[am], stA + aRow[am] + ((kc + xoff) ^ aSw[am]));
            #pragma unroll
            for (int bg = 0; bg < 4; bg++)
                ldsm_x4(b[bg], stB + bRow[bg] + ((kc + xoff) ^ bSw[bg]));

            #pragma unroll
            for (int am = 0; am < 2; am++)
                #pragma unroll
                for (int bg = 0; bg < 4; bg++) {
                    mma16816(d[am][bg * 2 + 0], a[am], b[bg][0], b[bg][2]);
                    mma16816(d[am][bg * 2 + 1], a[am], b[bg][1], b[bg][3]);
                }
        }

        if (lane == 0) {
            if (st == 0) MBAR_ARRIVE(sb + MB_EMPTY0);
            else         MBAR_ARRIVE(sb + MB_EMPTY1);
        }

        // Producer: refill this stage with chunk q+2 (may cross into next tile).
        if (tid == 0 && q + 2 < nq) {
            if (st == 0) { MBAR_WAIT(sb + MB_EMPTY0, (uint32_t)ep0); ep0 ^= 1; }
            else         { MBAR_WAIT(sb + MB_EMPTY1, (uint32_t)ep1); ep1 ^= 1; }
            const int qq = q + 2;
            bool mt, bd; const uint8_t *pA, *pB;
            tdecode((int)blockIdx.x + GRID * (qq >> 2), mt, bd, pA, pB);
            const int c = qq & 3;
            uint32_t fb = (st == 0) ? (sb + MB_FULL0) : (sb + MB_FULL1);
            MBAR_EXPECT_TX(fb, (uint32_t)STAGE_BYTES);
            BULK_G2S(stA, pA + c * KBLK_BYTES, KBLK_BYTES, fb);
            BULK_G2S(stB, pB + c * KBLK_BYTES, KBLK_BYTES, fb);
        }

        // Tile finished: epilogue (overlaps with next tile's in-flight loads).
        if ((q & 3) == 3) {
            bool maskt, bdiag; const uint8_t *uA, *uB;
            tdecode((int)blockIdx.x + GRID * (q >> 2), maskt, bdiag, uA, uB);

            if (!maskt && !bdiag) {
                #pragma unroll
                for (int am = 0; am < 2; am++)
                    #pragma unroll
                    for (int bn = 0; bn < 8; bn++)
                        #pragma unroll
                        for (int k = 0; k < 4; k++)
                            lsum += ex2f(d[am][bn][k] * EXP_HALF_LOG2E);
            } else if (maskt) {
                #pragma unroll
                for (int am = 0; am < 2; am++)
                    #pragma unroll
                    for (int bn = 0; bn < 8; bn++)
                        #pragma unroll
                        for (int k = 0; k < 4; k++) {
                            float e = ex2f(d[am][bn][k] * EXP_HALF_LOG2E);
                            int row = rbase + am * 16 + ((k >> 1) << 3);
                            int col = cbase + bn * 8 + (k & 1);
                            lsum += (col >= row) ? e : 0.0f;
                        }
            } else {  // bdiag
                #pragma unroll
                for (int am = 0; am < 2; am++)
                    #pragma unroll
                    for (int bn = 0; bn < 8; bn++)
                        #pragma unroll
                        for (int k = 0; k < 4; k++) {
                            float e = ex2f(d[am][bn][k] * EXP_HALF_LOG2E);
                            int row = rbase + am * 16 + ((k >> 1) << 3);
                            int col = cbase + bn * 8 + (k & 1);
                            lsum += e;
                            if (row == col) lsumd += e;
                        }
            }

            #pragma unroll
            for (int i = 0; i < 2; i++)
                #pragma unroll
                for (int j = 0; j < 8; j++)
                    #pragma unroll
                    for (int k = 0; k < 4; k++) d[i][j][k] = 0.0f;
        }
    }

    // ---- final CTA reduction: one atomic pair per CTA ----
    #pragma unroll
    for (int o = 16; o > 0; o >>= 1) {
        lsum  += __shfl_xor_sync(0xFFFFFFFFu, lsum,  o);
        lsumd += __shfl_xor_sync(0xFFFFFFFFu, lsumd, o);
    }
    __shared__ float wsum[8], wsumd[8];
    if (lane == 0) { wsum[wid] = lsum; wsumd[wid] = lsumd; }
    __syncthreads();
    if (tid == 0) {
        float s = 0.0f, sd = 0.0f;
        #pragma unroll
        for (int i = 0; i < 8; i++) { s += wsum[i]; sd += wsumd[i]; }
        atomicAdd(&g_main, (double)s);
        atomicAdd(&g_sims, (double)sd);
    }
}

// ---------------------------------------------------------------------------
__global__ void fin_k(float* __restrict__ out) {
    double sim_all = g_main + g_sims;
    out[0] = (float)(log(sim_all) - log(g_sims));
}

extern "C" void kernel_launch(void* const* d_in, const int* in_sizes, int n_in,
                              void* d_out, int out_size) {
    const float* x = (const float*)d_in[0];
    float* out = (float*)d_out;

    cudaFuncSetAttribute(tile_k, cudaFuncAttributeMaxDynamicSharedMemorySize, SMEM_TOTAL);

    normalize_k<<<NROWS / 8, 256>>>(x);
    tile_k<<<GRID, 256, SMEM_TOTAL>>>();
    fin_k<<<1, 1>>>(out);
}

// round 10
// speedup vs baseline: 1.1499x; 1.1499x over previous
#include <cuda_runtime.h>
#include <cuda_bf16.h>
#include <cuda_fp8.h>
#include <math.h>
#include <stdint.h>

// ContrastiveLoss via warp-level FP8 e4m3 mma.sync (m16n8k32, fp32 accum).
// loss = log(S_A_up + S_C_up + S_B_full + sim_s) - log(sim_s)
//   A=UU^T, C=VV^T, B=UV^T on L2-normalized halves (x16 pre-scale, folded
//   out in the exp constant). sim_s harvested from diagonal B tiles.
//
// g_x8: 64 bands of 128 rows; band = 2 K-blocks of 128 k-bytes = 128x128B,
// SW128-swizzled, 16KB contiguous -> cp.async.bulk feeds MMA smem directly.
// Outer structure identical to the verified 53.6us R5 kernel; K fully
// resident (2 chunks, both prefetched, no refills).

#define D      256
#define NROWS  8192
#define NT     32
#define BAND_BYTES 32768
#define KBLK_BYTES 16384
#define STAGE_BYTES 32768              // A 16KB + B 16KB
#define SMEM_DATA   1024
#define SMEM_TOTAL  (SMEM_DATA + 2 * STAGE_BYTES)   // 66560

#define MB_FULL0  16
#define MB_FULL1  24

__device__ __align__(128) uint8_t g_x8[NROWS * D];   // 2 MB fp8 swizzled
__device__ double g_main;
__device__ double g_sims;

// ---------------------------------------------------------------------------
static __device__ __forceinline__ uint32_t smem_u32(const void* p) {
    uint32_t a;
    asm("{ .reg .u64 t; cvta.to.shared.u64 t, %1; cvt.u32.u64 %0, t; }"
        : "=r"(a) : "l"(p));
    return a;
}

static __device__ __forceinline__ float ex2f(float x) {
    float y;
    asm("ex2.approx.f32 %0, %1;" : "=f"(y) : "f"(x));
    return y;
}
// rows scaled x16 -> dot = 256*cos; exp(cos/2) = exp2(dot * 0.5*log2(e)/256)
#define EXP_SC 2.8177637517362566e-3f

static __device__ __forceinline__ uint16_t fp8x2(float hi, float lo) {
    uint16_t r;
    asm("cvt.rn.satfinite.e4m3x2.f32 %0, %1, %2;" : "=h"(r) : "f"(hi), "f"(lo));
    return r;
}

#define MBAR_INIT(addr, cnt) \
    asm volatile("mbarrier.init.shared.b64 [%0], %1;" :: "r"(addr), "r"(cnt) : "memory")

#define MBAR_EXPECT_TX(addr, bytes) \
    asm volatile("mbarrier.arrive.expect_tx.shared.b64 _, [%0], %1;" \
                 :: "r"(addr), "r"(bytes) : "memory")

#define MBAR_WAIT(addr, parity) do {                                          \
    uint32_t _m = (addr); uint32_t _p = (parity); uint32_t _done;             \
    asm volatile("{\n\t.reg .pred p;\n\t"                                     \
        "mbarrier.try_wait.parity.acquire.cta.shared::cta.b64 p, [%1], %2;\n\t"\
        "selp.b32 %0, 1, 0, p;\n\t}"                                          \
        : "=r"(_done) : "r"(_m), "r"(_p) : "memory");                         \
    if (!_done) {                                                             \
        asm volatile("{\n\t.reg .pred P1;\n\t"                                \
            "W_%=:\n\t"                                                       \
            "mbarrier.try_wait.parity.acquire.cta.shared::cta.b64 P1, [%0], %1, 0x989680;\n\t" \
            "@P1 bra.uni WD_%=;\n\t"                                          \
            "bra.uni W_%=;\n\t"                                               \
            "WD_%=:\n\t}" :: "r"(_m), "r"(_p) : "memory");                    \
    }                                                                         \
} while (0)

#define BULK_G2S(dst, src, bytes, mbar) \
    asm volatile("cp.async.bulk.shared::cta.global.mbarrier::complete_tx::bytes [%0], [%1], %2, [%3];" \
                 :: "r"(dst), "l"(src), "r"(bytes), "r"(mbar) : "memory")

static __device__ __forceinline__ void ldsm_x4(uint32_t* r, uint32_t addr) {
    asm volatile("ldmatrix.sync.aligned.m8n8.x4.shared.b16 {%0,%1,%2,%3}, [%4];"
                 : "=r"(r[0]), "=r"(r[1]), "=r"(r[2]), "=r"(r[3]) : "r"(addr));
}

static __device__ __forceinline__ void mma_e4m3(float* d, const uint32_t* a,
                                                uint32_t b0, uint32_t b1) {
    asm volatile("mma.sync.aligned.m16n8k32.row.col.f32.e4m3.e4m3.f32 "
                 "{%0,%1,%2,%3}, {%4,%5,%6,%7}, {%8,%9}, {%0,%1,%2,%3};"
                 : "+f"(d[0]), "+f"(d[1]), "+f"(d[2]), "+f"(d[3])
                 : "r"(a[0]), "r"(a[1]), "r"(a[2]), "r"(a[3]), "r"(b0), "r"(b1));
}

// ---------------------------------------------------------------------------
// Warp per row: L2 norm -> fp8(v*inv*16) into swizzled band layout.
// Block 0 also zeroes global accumulators (stream-ordered before tile_k).
__global__ __launch_bounds__(256) void normalize_k(const float* __restrict__ x) {
    const int tid  = threadIdx.x;
    const int wid  = tid >> 5;
    const int lane = tid & 31;
    const int row  = blockIdx.x * 8 + wid;
    if (blockIdx.x == 0 && tid == 0) { g_main = 0.0; g_sims = 0.0; }

    const float4* xr = (const float4*)(x + row * D);
    float4 v0 = xr[lane * 2 + 0];
    float4 v1 = xr[lane * 2 + 1];

    float ss = v0.x * v0.x + v0.y * v0.y + v0.z * v0.z + v0.w * v0.w
             + v1.x * v1.x + v1.y * v1.y + v1.z * v1.z + v1.w * v1.w;
    #pragma unroll
    for (int o = 16; o > 0; o >>= 1) ss += __shfl_xor_sync(0xFFFFFFFFu, ss, o);
    float s16 = 16.0f / fmaxf(sqrtf(ss), 1e-8f);

    uint16_t h0 = fp8x2(v0.y * s16, v0.x * s16);   // bytes k0,k1 (lo=k0)
    uint16_t h1 = fp8x2(v0.w * s16, v0.z * s16);
    uint16_t h2 = fp8x2(v1.y * s16, v1.x * s16);
    uint16_t h3 = fp8x2(v1.w * s16, v1.z * s16);
    uint32_t w0 = (uint32_t)h0 | ((uint32_t)h1 << 16);
    uint32_t w1 = (uint32_t)h2 | ((uint32_t)h3 << 16);

    // lane covers k = lane*8 .. lane*8+7 -> 8 contiguous bytes, 8B-aligned
    // (SW128 XOR touches bits [6:4] only -> 8B stores stay intact).
    int band = row >> 7, rib = row & 127;
    int kb = lane >> 4;                                   // K-block (128 k)
    uint32_t off = (uint32_t)(rib * 128 + (lane & 15) * 8);
    off ^= (off >> 3) & 0x70;                             // SW128
    uint2 w; w.x = w0; w.y = w1;
    *(uint2*)(g_x8 + (size_t)band * BAND_BYTES + (size_t)kb * KBLK_BYTES + off) = w;
}

// ---------------------------------------------------------------------------
// One CTA = one 128x128x256 tile. 1024 B-full + 528 A-upper + 528 C-upper.
__global__ __launch_bounds__(256, 2) void tile_k() {
    extern __shared__ __align__(1024) uint8_t smem[];
    uint32_t sb = smem_u32(smem);
    const int tid  = threadIdx.x;
    const int wid  = tid >> 5;
    const int lane = tid & 31;

    // ---- tile decode ----
    int t = blockIdx.x;
    int bi, bj;
    bool maskt = false, bdiag = false;
    const uint8_t *gA, *gB;
    if (t < 1024) {                       // B = U V^T, full
        bi = t >> 5; bj = t & 31;
        bdiag = (bi == bj);               // carries diag(B) -> sim_s
        gA = g_x8 + (size_t)bi * BAND_BYTES;
        gB = g_x8 + (size_t)(32 + bj) * BAND_BYTES;
    } else {                              // A (m=0) / C (m=1), upper
        t -= 1024;
        int m = (t >= 528) ? 1 : 0;
        int u = t - m * 528;
        int b_ = 0;
        while (u >= NT - b_) { u -= NT - b_; b_++; }
        bi = b_; bj = b_ + u;
        maskt = (bi == bj);
        gA = g_x8 + (size_t)(m * 32 + bi) * BAND_BYTES;
        gB = g_x8 + (size_t)(m * 32 + bj) * BAND_BYTES;
    }

    if (tid == 0) {
        MBAR_INIT(sb + MB_FULL0, 1);
        MBAR_INIT(sb + MB_FULL1, 1);
    }
    __syncthreads();

    if (tid == 0) {
        #pragma unroll
        for (int s = 0; s < 2; s++) {
            uint32_t stb = sb + SMEM_DATA + s * STAGE_BYTES;
            uint32_t fb  = sb + MB_FULL0 + 8 * s;
            MBAR_EXPECT_TX(fb, (uint32_t)STAGE_BYTES);
            BULK_G2S(stb,         gA + s * KBLK_BYTES, KBLK_BYTES, fb);
            BULK_G2S(stb + 16384, gB + s * KBLK_BYTES, KBLK_BYTES, fb);
        }
    }

    // ---- per-warp / per-lane ldmatrix geometry (byte-frag, verified R4) ----
    const int warp_m = wid & 3;          // 32-row strip
    const int warp_n = wid >> 2;         // 64-col strip
    const int g      = lane >> 3;
    const uint32_t sw = (uint32_t)((lane & 7) << 4);

    uint32_t aRow[2];
    const uint32_t aKh = (uint32_t)((g >> 1) * 16);
    #pragma unroll
    for (int am = 0; am < 2; am++) {
        int r = warp_m * 32 + am * 16 + (g & 1) * 8 + (lane & 7);
        aRow[am] = (uint32_t)(r * 128);
    }
    uint32_t bRow[4];
    const uint32_t bKh = (uint32_t)((g & 1) * 16);
    #pragma unroll
    for (int bg = 0; bg < 4; bg++) {
        int r = warp_n * 64 + bg * 16 + (g >> 1) * 8 + (lane & 7);
        bRow[bg] = (uint32_t)(r * 128);
    }

    float d[2][8][4];
    #pragma unroll
    for (int i = 0; i < 2; i++)
        #pragma unroll
        for (int j = 0; j < 8; j++)
            #pragma unroll
            for (int k = 0; k < 4; k++) d[i][j][k] = 0.0f;

    // ---- mainloop: 2 chunks of K=128, 4 k32-steps each, fully unrolled ----
    #pragma unroll
    for (int c = 0; c < 2; c++) {
        const uint32_t stA = sb + SMEM_DATA + c * STAGE_BYTES;
        const uint32_t stB = stA + 16384;
        MBAR_WAIT(sb + MB_FULL0 + 8 * c, 0u);

        #pragma unroll
        for (int ks = 0; ks < 4; ks++) {
            const uint32_t kc = (uint32_t)(ks * 32);
            uint32_t a[2][4], b[4][4];
            #pragma unroll
            for (int am = 0; am < 2; am++)
                ldsm_x4(a[am], stA + aRow[am] + ((kc + aKh) ^ sw));
            #pragma unroll
            for (int bg = 0; bg < 4; bg++)
                ldsm_x4(b[bg], stB + bRow[bg] + ((kc + bKh) ^ sw));

            #pragma unroll
            for (int am = 0; am < 2; am++)
                #pragma unroll
                for (int bg = 0; bg < 4; bg++) {
                    mma_e4m3(d[am][bg * 2 + 0], a[am], b[bg][0], b[bg][1]);
                    mma_e4m3(d[am][bg * 2 + 1], a[am], b[bg][2], b[bg][3]);
                }
        }
    }

    // ---- epilogue: exp2(d * EXP_SC) -> reduce; uniform tile-type branch ----
    const int rbase = warp_m * 32 + (lane >> 2);
    const int cbase = warp_n * 64 + 2 * (lane & 3);
    float sum = 0.0f;
    float sumd = 0.0f;

    if (!maskt && !bdiag) {
        #pragma unroll
        for (int am = 0; am < 2; am++)
            #pragma unroll
            for (int bn = 0; bn < 8; bn++)
                #pragma unroll
                for (int k = 0; k < 4; k++)
                    sum += ex2f(d[am][bn][k] * EXP_SC);
    } else if (maskt) {
        #pragma unroll
        for (int am = 0; am < 2; am++)
            #pragma unroll
            for (int bn = 0; bn < 8; bn++)
                #pragma unroll
                for (int k = 0; k < 4; k++) {
                    float e = ex2f(d[am][bn][k] * EXP_SC);
                    int row = rbase + am * 16 + ((k >> 1) << 3);
                    int col = cbase + bn * 8 + (k & 1);
                    sum += (col >= row) ? e : 0.0f;
                }
    } else {  // bdiag: full sum + harvest diagonal into sim_s
        #pragma unroll
        for (int am = 0; am < 2; am++)
            #pragma unroll
            for (int bn = 0; bn < 8; bn++)
                #pragma unroll
                for (int k = 0; k < 4; k++) {
                    float e = ex2f(d[am][bn][k] * EXP_SC);
                    int row = rbase + am * 16 + ((k >> 1) << 3);
                    int col = cbase + bn * 8 + (k & 1);
                    sum += e;
                    if (row == col) sumd += e;
                }
    }

    #pragma unroll
    for (int o = 16; o > 0; o >>= 1)
        sum += __shfl_xor_sync(0xFFFFFFFFu, sum, o);

    __shared__ float wsum[8];
    if (lane == 0) wsum[wid] = sum;

    if (bdiag) {
        #pragma unroll
        for (int o = 16; o > 0; o >>= 1)
            sumd += __shfl_xor_sync(0xFFFFFFFFu, sumd, o);
        __shared__ float wsumd[8];
        if (lane == 0) wsumd[wid] = sumd;
        __syncthreads();
        if (tid == 0) {
            float s = 0.0f, sd = 0.0f;
            #pragma unroll
            for (int i = 0; i < 8; i++) { s += wsum[i]; sd += wsumd[i]; }
            atomicAdd(&g_main, (double)s);
            atomicAdd(&g_sims, (double)sd);
        }
    } else {
        __syncthreads();
        if (tid == 0) {
            float s = 0.0f;
            #pragma unroll
            for (int i = 0; i < 8; i++) s += wsum[i];
            atomicAdd(&g_main, (double)s);
        }
    }
}

// ---------------------------------------------------------------------------
__global__ void fin_k(float* __restrict__ out) {
    double sim_all = g_main + g_sims;
    out[0] = (float)(log(sim_all) - log(g_sims));
}

extern "C" void kernel_launch(void* const* d_in, const int* in_sizes, int n_in,
                              void* d_out, int out_size) {
    const float* x = (const float*)d_in[0];
    float* out = (float*)d_out;

    cudaFuncSetAttribute(tile_k, cudaFuncAttributeMaxDynamicSharedMemorySize, SMEM_TOTAL);

    normalize_k<<<NROWS / 8, 256>>>(x);
    tile_k<<<1024 + 2 * 528, 256, SMEM_TOTAL>>>();
    fin_k<<<1, 1>>>(out);
}

// round 11
// speedup vs baseline: 1.2293x; 1.0691x over previous
#include <cuda_runtime.h>
#include <cuda_bf16.h>
#include <math.h>
#include <stdint.h>

// ContrastiveLoss via warp-level bf16 mma.sync (HMMA), 2 launches.
// loss = log(S_A_up + S_C_up + S_B_full + sim_s) - log(sim_s)
//   A=UU^T, C=VV^T, B=UV^T on L2-normalized halves.
//   sim_s = sum exp(diag(B)/2), harvested from the 32 diagonal B tiles.
// Final log folded into tile_k's last-finishing CTA (fp32 only -- DP log in
// R7 caused accumulator spills under the 128-reg cap; __logf keeps pressure
// flat).
//
// g_xb: 64 bands of 128 rows; band = 4 K-blocks of 64 bf16 = 128 rows x 128B,
// SW128-swizzled, 16KB contiguous -> cp.async.bulk feeds MMA smem directly.

#define D      256
#define NROWS  8192
#define NT     32
#define NTILES 2080
#define BAND_BYTES 65536
#define KBLK_BYTES 16384
#define STAGE_BYTES 32768              // A 16KB + B 16KB
#define SMEM_DATA   1024
#define SMEM_TOTAL  (SMEM_DATA + 2 * STAGE_BYTES)   // 66560

#define MB_FULL0  16
#define MB_FULL1  24
#define MB_EMPTY0 32
#define MB_EMPTY1 40

__device__ __align__(128) uint8_t g_xb[NROWS * D * 2];   // 4 MB bf16 swizzled
__device__ double g_main;
__device__ double g_sims;
__device__ int    g_done;

// ---------------------------------------------------------------------------
static __device__ __forceinline__ uint32_t smem_u32(const void* p) {
    uint32_t a;
    asm("{ .reg .u64 t; cvta.to.shared.u64 t, %1; cvt.u32.u64 %0, t; }"
        : "=r"(a) : "l"(p));
    return a;
}

static __device__ __forceinline__ float ex2f(float x) {
    float y;
    asm("ex2.approx.f32 %0, %1;" : "=f"(y) : "f"(x));
    return y;
}
#define EXP_HALF_LOG2E 0.7213475204444817f   // 0.5 * log2(e)

static __device__ __forceinline__ float lg2f(float x) {
    float y;
    asm("lg2.approx.f32 %0, %1;" : "=f"(y) : "f"(x));
    return y;
}
#define LN2F 0.6931471805599453f

#define MBAR_INIT(addr, cnt) \
    asm volatile("mbarrier.init.shared.b64 [%0], %1;" :: "r"(addr), "r"(cnt) : "memory")

#define MBAR_ARRIVE(addr) \
    asm volatile("mbarrier.arrive.shared.b64 _, [%0];" :: "r"(addr) : "memory")

#define MBAR_EXPECT_TX(addr, bytes) \
    asm volatile("mbarrier.arrive.expect_tx.shared.b64 _, [%0], %1;" \
                 :: "r"(addr), "r"(bytes) : "memory")

#define MBAR_WAIT(addr, parity) do {                                          \
    uint32_t _m = (addr); uint32_t _p = (parity); uint32_t _done;             \
    asm volatile("{\n\t.reg .pred p;\n\t"                                     \
        "mbarrier.try_wait.parity.acquire.cta.shared::cta.b64 p, [%1], %2;\n\t"\
        "selp.b32 %0, 1, 0, p;\n\t}"                                          \
        : "=r"(_done) : "r"(_m), "r"(_p) : "memory");                         \
    if (!_done) {                                                             \
        asm volatile("{\n\t.reg .pred P1;\n\t"                                \
            "W_%=:\n\t"                                                       \
            "mbarrier.try_wait.parity.acquire.cta.shared::cta.b64 P1, [%0], %1, 0x989680;\n\t" \
            "@P1 bra.uni WD_%=;\n\t"                                          \
            "bra.uni W_%=;\n\t"                                               \
            "WD_%=:\n\t}" :: "r"(_m), "r"(_p) : "memory");                    \
    }                                                                         \
} while (0)

#define BULK_G2S(dst, src, bytes, mbar) \
    asm volatile("cp.async.bulk.shared::cta.global.mbarrier::complete_tx::bytes [%0], [%1], %2, [%3];" \
                 :: "r"(dst), "l"(src), "r"(bytes), "r"(mbar) : "memory")

static __device__ __forceinline__ void ldsm_x4(uint32_t* r, uint32_t addr) {
    asm volatile("ldmatrix.sync.aligned.m8n8.x4.shared.b16 {%0,%1,%2,%3}, [%4];"
                 : "=r"(r[0]), "=r"(r[1]), "=r"(r[2]), "=r"(r[3]) : "r"(addr));
}

static __device__ __forceinline__ void mma16816(float* d, const uint32_t* a,
                                                uint32_t b0, uint32_t b1) {
    asm volatile("mma.sync.aligned.m16n8k16.row.col.f32.bf16.bf16.f32 "
                 "{%0,%1,%2,%3}, {%4,%5,%6,%7}, {%8,%9}, {%0,%1,%2,%3};"
                 : "+f"(d[0]), "+f"(d[1]), "+f"(d[2]), "+f"(d[3])
                 : "r"(a[0]), "r"(a[1]), "r"(a[2]), "r"(a[3]), "r"(b0), "r"(b1));
}

// ---------------------------------------------------------------------------
// Two rows per warp (interleaved shfl chains for ILP). Block 0 zeroes
// accumulators (stream-ordered before tile_k on every graph replay).
__global__ __launch_bounds__(256) void normalize_k(const float* __restrict__ x) {
    const int tid  = threadIdx.x;
    const int wid  = tid >> 5;
    const int lane = tid & 31;
    const int r0   = blockIdx.x * 16 + wid * 2;
    const int r1   = r0 + 1;
    if (blockIdx.x == 0 && tid == 0) { g_main = 0.0; g_sims = 0.0; }

    const float4* x0 = (const float4*)(x + r0 * D);
    const float4* x1 = (const float4*)(x + r1 * D);
    float4 a0 = x0[lane * 2 + 0];
    float4 a1 = x0[lane * 2 + 1];
    float4 b0 = x1[lane * 2 + 0];
    float4 b1 = x1[lane * 2 + 1];

    float sa = a0.x * a0.x + a0.y * a0.y + a0.z * a0.z + a0.w * a0.w
             + a1.x * a1.x + a1.y * a1.y + a1.z * a1.z + a1.w * a1.w;
    float sb = b0.x * b0.x + b0.y * b0.y + b0.z * b0.z + b0.w * b0.w
             + b1.x * b1.x + b1.y * b1.y + b1.z * b1.z + b1.w * b1.w;
    #pragma unroll
    for (int o = 16; o > 0; o >>= 1) {
        sa += __shfl_xor_sync(0xFFFFFFFFu, sa, o);
        sb += __shfl_xor_sync(0xFFFFFFFFu, sb, o);
    }
    float ia = 1.0f / fmaxf(sqrtf(sa), 1e-8f);
    float ib = 1.0f / fmaxf(sqrtf(sb), 1e-8f);

    uint32_t pa[4], pb[4];
    pa[0] = (uint32_t)__bfloat16_as_ushort(__float2bfloat16(a0.x * ia))
          | ((uint32_t)__bfloat16_as_ushort(__float2bfloat16(a0.y * ia)) << 16);
    pa[1] = (uint32_t)__bfloat16_as_ushort(__float2bfloat16(a0.z * ia))
          | ((uint32_t)__bfloat16_as_ushort(__float2bfloat16(a0.w * ia)) << 16);
    pa[2] = (uint32_t)__bfloat16_as_ushort(__float2bfloat16(a1.x * ia))
          | ((uint32_t)__bfloat16_as_ushort(__float2bfloat16(a1.y * ia)) << 16);
    pa[3] = (uint32_t)__bfloat16_as_ushort(__float2bfloat16(a1.z * ia))
          | ((uint32_t)__bfloat16_as_ushort(__float2bfloat16(a1.w * ia)) << 16);
    pb[0] = (uint32_t)__bfloat16_as_ushort(__float2bfloat16(b0.x * ib))
          | ((uint32_t)__bfloat16_as_ushort(__float2bfloat16(b0.y * ib)) << 16);
    pb[1] = (uint32_t)__bfloat16_as_ushort(__float2bfloat16(b0.z * ib))
          | ((uint32_t)__bfloat16_as_ushort(__float2bfloat16(b0.w * ib)) << 16);
    pb[2] = (uint32_t)__bfloat16_as_ushort(__float2bfloat16(b1.x * ib))
          | ((uint32_t)__bfloat16_as_ushort(__float2bfloat16(b1.y * ib)) << 16);
    pb[3] = (uint32_t)__bfloat16_as_ushort(__float2bfloat16(b1.z * ib))
          | ((uint32_t)__bfloat16_as_ushort(__float2bfloat16(b1.w * ib)) << 16);

    // lane covers k = lane*8 .. lane*8+7 -> 16 contiguous bytes, 16B-aligned.
    const int band = r0 >> 7;
    const int kb   = lane >> 3;
    uint8_t* bandp = g_xb + (size_t)band * BAND_BYTES + (size_t)kb * KBLK_BYTES;
    uint32_t o0 = (uint32_t)((r0 & 127) * 128 + (lane & 7) * 16);
    uint32_t o1 = o0 + 128;
    o0 ^= (o0 >> 3) & 0x70;
    o1 ^= (o1 >> 3) & 0x70;
    *(uint4*)(bandp + o0) = *(uint4*)pa;
    *(uint4*)(bandp + o1) = *(uint4*)pb;
}

// ---------------------------------------------------------------------------
// One CTA = one 128x128x256 tile. Mainloop/epilogue byte-identical to the
// verified 53.6us R5 kernel; only the tail gains the fp32 finalizer.
__global__ __launch_bounds__(256, 2) void tile_k(float* __restrict__ out) {
    extern __shared__ __align__(1024) uint8_t smem[];
    uint32_t sb = smem_u32(smem);
    const int tid  = threadIdx.x;
    const int wid  = tid >> 5;
    const int lane = tid & 31;

    // ---- tile decode ----
    int t = blockIdx.x;
    int bi, bj;
    bool maskt = false, bdiag = false;
    const uint8_t *gA, *gB;
    if (t < 1024) {                       // B = U V^T, full
        bi = t >> 5; bj = t & 31;
        bdiag = (bi == bj);               // carries diag(B) -> sim_s
        gA = g_xb + (size_t)bi * BAND_BYTES;
        gB = g_xb + (size_t)(32 + bj) * BAND_BYTES;
    } else {                              // A (m=0) / C (m=1), upper
        t -= 1024;
        int m = (t >= 528) ? 1 : 0;
        int u = t - m * 528;
        int b_ = 0;
        while (u >= NT - b_) { u -= NT - b_; b_++; }
        bi = b_; bj = b_ + u;
        maskt = (bi == bj);
        gA = g_xb + (size_t)(m * 32 + bi) * BAND_BYTES;
        gB = g_xb + (size_t)(m * 32 + bj) * BAND_BYTES;
    }

    if (tid == 0) {
        MBAR_INIT(sb + MB_FULL0, 1);  MBAR_INIT(sb + MB_FULL1, 1);
        MBAR_INIT(sb + MB_EMPTY0, 8); MBAR_INIT(sb + MB_EMPTY1, 8);
    }
    __syncthreads();

    if (tid == 0) {
        #pragma unroll
        for (int s = 0; s < 2; s++) {
            uint32_t stb = sb + SMEM_DATA + s * STAGE_BYTES;
            uint32_t fb  = sb + MB_FULL0 + 8 * s;
            MBAR_EXPECT_TX(fb, (uint32_t)STAGE_BYTES);
            BULK_G2S(stb,         gA + s * KBLK_BYTES, KBLK_BYTES, fb);
            BULK_G2S(stb + 16384, gB + s * KBLK_BYTES, KBLK_BYTES, fb);
        }
    }

    // ---- per-warp / per-lane ldmatrix geometry (verified R3/R5) ----
    const int warp_m = wid & 3;          // 32-row strip
    const int warp_n = wid >> 2;         // 64-col strip
    const int lrow = lane & 15;
    const uint32_t xoff = ((lane >> 4) & 1) * 16;

    uint32_t aRow[2], aSw[2], bRow[4], bSw[4];
    #pragma unroll
    for (int am = 0; am < 2; am++) {
        int r = warp_m * 32 + am * 16 + lrow;
        aRow[am] = (uint32_t)(r * 128);
        aSw[am]  = (uint32_t)((r & 7) << 4);
    }
    #pragma unroll
    for (int bg = 0; bg < 4; bg++) {
        int r = warp_n * 64 + bg * 16 + lrow;
        bRow[bg] = (uint32_t)(r * 128);
        bSw[bg]  = (uint32_t)((r & 7) << 4);
    }

    float d[2][8][4];
    #pragma unroll
    for (int i = 0; i < 2; i++)
        #pragma unroll
        for (int j = 0; j < 8; j++)
            #pragma unroll
            for (int k = 0; k < 4; k++) d[i][j][k] = 0.0f;

    // ---- chunk loop: 4 chunks of K=64, double-buffered ----
    #pragma unroll
    for (int c = 0; c < 4; c++) {
        const int st = c & 1;
        const uint32_t stA = sb + SMEM_DATA + st * STAGE_BYTES;
        const uint32_t stB = stA + 16384;
        MBAR_WAIT(sb + MB_FULL0 + 8 * st, (uint32_t)((c >> 1) & 1));

        #pragma unroll
        for (int ks = 0; ks < 4; ks++) {
            const uint32_t kc = (uint32_t)(ks * 32);
            uint32_t a[2][4], b[4][4];
            #pragma unroll
            for (int am = 0; am < 2; am++)
                ldsm_x4(a[am], stA + aRow[am] + ((kc + xoff) ^ aSw[am]));
            #pragma unroll
            for (int bg = 0; bg < 4; bg++)
                ldsm_x4(b[bg], stB + bRow[bg] + ((kc + xoff) ^ bSw[bg]));

            #pragma unroll
            for (int am = 0; am < 2; am++)
                #pragma unroll
                for (int bg = 0; bg < 4; bg++) {
                    mma16816(d[am][bg * 2 + 0], a[am], b[bg][0], b[bg][2]);
                    mma16816(d[am][bg * 2 + 1], a[am], b[bg][1], b[bg][3]);
                }
        }

        if (lane == 0) MBAR_ARRIVE(sb + MB_EMPTY0 + 8 * st);
        if (tid == 0 && c < 2) {
            MBAR_WAIT(sb + MB_EMPTY0 + 8 * st, 0u);
            uint32_t fb = sb + MB_FULL0 + 8 * st;
            MBAR_EXPECT_TX(fb, (uint32_t)STAGE_BYTES);
            BULK_G2S(stA, gA + (c + 2) * KBLK_BYTES, KBLK_BYTES, fb);
            BULK_G2S(stB, gB + (c + 2) * KBLK_BYTES, KBLK_BYTES, fb);
        }
    }

    // ---- epilogue: exp2(d * 0.5*log2 e) -> reduce; uniform tile-type branch ----
    const int rbase = warp_m * 32 + (lane >> 2);
    const int cbase = warp_n * 64 + 2 * (lane & 3);
    float sum = 0.0f;
    float sumd = 0.0f;

    if (!maskt && !bdiag) {
        #pragma unroll
        for (int am = 0; am < 2; am++)
            #pragma unroll
            for (int bn = 0; bn < 8; bn++)
                #pragma unroll
                for (int k = 0; k < 4; k++)
                    sum += ex2f(d[am][bn][k] * EXP_HALF_LOG2E);
    } else if (maskt) {
        #pragma unroll
        for (int am = 0; am < 2; am++)
            #pragma unroll
            for (int bn = 0; bn < 8; bn++)
                #pragma unroll
                for (int k = 0; k < 4; k++) {
                    float e = ex2f(d[am][bn][k] * EXP_HALF_LOG2E);
                    int row = rbase + am * 16 + ((k >> 1) << 3);
                    int col = cbase + bn * 8 + (k & 1);
                    sum += (col >= row) ? e : 0.0f;
                }
    } else {  // bdiag: full sum + harvest diagonal into sim_s
        #pragma unroll
        for (int am = 0; am < 2; am++)
            #pragma unroll
            for (int bn = 0; bn < 8; bn++)
                #pragma unroll
                for (int k = 0; k < 4; k++) {
                    float e = ex2f(d[am][bn][k] * EXP_HALF_LOG2E);
                    int row = rbase + am * 16 + ((k >> 1) << 3);
                    int col = cbase + bn * 8 + (k & 1);
                    sum += e;
                    if (row == col) sumd += e;
                }
    }

    #pragma unroll
    for (int o = 16; o > 0; o >>= 1)
        sum += __shfl_xor_sync(0xFFFFFFFFu, sum, o);

    __shared__ float wsum[8];
    if (lane == 0) wsum[wid] = sum;

    if (bdiag) {
        #pragma unroll
        for (int o = 16; o > 0; o >>= 1)
            sumd += __shfl_xor_sync(0xFFFFFFFFu, sumd, o);
        __shared__ float wsumd[8];
        if (lane == 0) wsumd[wid] = sumd;
        __syncthreads();
        if (tid == 0) {
            float s = 0.0f, sd = 0.0f;
            #pragma unroll
            for (int i = 0; i < 8; i++) { s += wsum[i]; sd += wsumd[i]; }
            atomicAdd(&g_main, (double)s);
            atomicAdd(&g_sims, (double)sd);
        }
    } else {
        __syncthreads();
        if (tid == 0) {
            float s = 0.0f;
            #pragma unroll
            for (int i = 0; i < 8; i++) s += wsum[i];
            atomicAdd(&g_main, (double)s);
        }
    }

    // ---- finalizer: last CTA computes the loss (fp32 only; cold branch) ----
    if (tid == 0) {
        __threadfence();
        int prev = atomicAdd(&g_done, 1);
        if (prev == NTILES - 1) {
            float mn   = (float)atomicAdd(&g_main, 0.0);   // coherent read
            float sims = (float)atomicAdd(&g_sims, 0.0);
            out[0] = lg2f((mn + sims) / sims) * LN2F;
            g_done = 0;                                    // replay-safe reset
            __threadfence();
        }
    }
}

// ---------------------------------------------------------------------------
extern "C" void kernel_launch(void* const* d_in, const int* in_sizes, int n_in,
                              void* d_out, int out_size) {
    const float* x = (const float*)d_in[0];
    float* out = (float*)d_out;

    cudaFuncSetAttribute(tile_k, cudaFuncAttributeMaxDynamicSharedMemorySize, SMEM_TOTAL);

    normalize_k<<<NROWS / 16, 256>>>(x);
    tile_k<<<NTILES, 256, SMEM_TOTAL>>>(out);
}